// round 3
// baseline (speedup 1.0000x reference)
#include <cuda_runtime.h>
#include <cuda_fp16.h>
#include <cstdint>

// ---------------- problem dims ----------------
constexpr int B_ = 4, E_ = 8, C_ = 2048, D_ = 1024, F_ = 2816;

// ---------------- device scratch (allocation-free) ----------------
__device__ __half g_xh [(size_t)B_ * E_ * C_ * D_];   // X fp16 [be][C][D]
__device__ __half g_w1t[(size_t)E_ * F_ * D_];        // w1^T fp16 [e][F][D]
__device__ __half g_w3t[(size_t)E_ * F_ * D_];        // w3^T fp16 [e][F][D]
__device__ __half g_w2t[(size_t)E_ * D_ * F_];        // w2^T fp16 [e][D][F]
__device__ __half g_hh [(size_t)B_ * E_ * C_ * F_];   // H fp16 [be][C][F]

// ---------------- PTX helpers ----------------
__device__ __forceinline__ uint32_t smem_u32(const void* p) {
    return (uint32_t)__cvta_generic_to_shared(p);
}
__device__ __forceinline__ void cp16(uint32_t saddr, const void* g) {
    asm volatile("cp.async.cg.shared.global [%0], [%1], 16;\n" ::"r"(saddr), "l"(g));
}
__device__ __forceinline__ void cp_commit() {
    asm volatile("cp.async.commit_group;\n");
}
__device__ __forceinline__ void cp_wait2() {
    asm volatile("cp.async.wait_group 2;\n");
}
__device__ __forceinline__ void ldsm4(uint32_t* r, uint32_t addr) {
    asm volatile("ldmatrix.sync.aligned.m8n8.x4.shared.b16 {%0,%1,%2,%3}, [%4];"
                 : "=r"(r[0]), "=r"(r[1]), "=r"(r[2]), "=r"(r[3])
                 : "r"(addr));
}
__device__ __forceinline__ void mma16816(float* d, const uint32_t* a, uint32_t b0, uint32_t b1) {
    asm volatile(
        "mma.sync.aligned.m16n8k16.row.col.f32.f16.f16.f32 "
        "{%0,%1,%2,%3}, {%4,%5,%6,%7}, {%8,%9}, {%0,%1,%2,%3};"
        : "+f"(d[0]), "+f"(d[1]), "+f"(d[2]), "+f"(d[3])
        : "r"(a[0]), "r"(a[1]), "r"(a[2]), "r"(a[3]), "r"(b0), "r"(b1));
}

// ---------------- convert kernels ----------------
__global__ void cvt_kernel(const float4* __restrict__ in, __half2* __restrict__ out, int n4) {
    int i = blockIdx.x * 256 + threadIdx.x;
    if (i >= n4) return;
    float4 v = in[i];
    out[2 * i + 0] = __floats2half2_rn(v.x, v.y);
    out[2 * i + 1] = __floats2half2_rn(v.z, v.w);
}

// in: [R, Ccols] fp32 per expert  ->  out: [Ccols, R] fp16 per expert
__global__ void cvtT_kernel(const float* __restrict__ in, __half* __restrict__ out,
                            int R, int Ccols) {
    __shared__ float t[32][33];
    const float* ine  = in  + (size_t)blockIdx.z * R * Ccols;
    __half*      oute = out + (size_t)blockIdx.z * R * Ccols;
    int c0 = blockIdx.x * 32, r0 = blockIdx.y * 32;
    int tx = threadIdx.x, ty = threadIdx.y;   // 32 x 8
#pragma unroll
    for (int i = 0; i < 4; i++)
        t[ty + 8 * i][tx] = ine[(size_t)(r0 + ty + 8 * i) * Ccols + c0 + tx];
    __syncthreads();
#pragma unroll
    for (int i = 0; i < 4; i++)
        oute[(size_t)(c0 + ty + 8 * i) * R + r0 + tx] = __float2half_rn(t[tx][ty + 8 * i]);
}

// ============================================================
// mma.sync GEMM, 256 threads, CTA: 128 A-rows x 256 B-rows, BK=32, 4 stages.
// SMEM rows are 32 halfs (64B data) at 80B stride -> ldmatrix conflict-free.
// GEMM1 (G1=1): A=X[128,1024], B=[w1t n0..n0+127 ; w3t n0..n0+127],
//               epilogue SwiGLU -> H fp16 tile [128 x 128].
// GEMM2 (G1=0): A=H[128,2816], B=w2t rows n0..n0+255 -> out fp32 [128 x 256].
// ============================================================
constexpr int ROWB   = 80;                    // bytes per smem row
constexpr int A_BYTES = 128 * ROWB;           // 10240
constexpr int B_BYTES = 256 * ROWB;           // 20480
constexpr int STG     = A_BYTES + B_BYTES;    // 30720
constexpr int DYNSM   = 4 * STG;              // 122880

template <int G1>
__global__ __launch_bounds__(256) void gemm_mma(float* __restrict__ out) {
    extern __shared__ __align__(128) char smem[];

    const int tid  = threadIdx.x;
    const int wid  = tid >> 5;
    const int lane = tid & 31;
    const int be   = blockIdx.z, e = be & 7;
    const int m0   = blockIdx.y * 128;
    const int n0   = blockIdx.x * (G1 ? 128 : 256);

    constexpr int LDA = G1 ? D_ : F_;
    constexpr int LDB = G1 ? D_ : F_;
    constexpr int NK  = G1 ? (D_ / 32) : (F_ / 32);   // 32 : 88

    const __half* A = (G1 ? g_xh : g_hh) + ((size_t)be * C_ + m0) * LDA;
    const __half* B0;
    const __half* B1w = nullptr;
    if (G1) {
        B0  = g_w1t + (size_t)e * F_ * D_ + (size_t)n0 * D_;
        B1w = g_w3t + (size_t)e * F_ * D_ + (size_t)n0 * D_;
    } else {
        B0 = g_w2t + (size_t)e * D_ * F_ + (size_t)n0 * F_;
    }

    const uint32_t sb = smem_u32(smem);

    // ------- stage loader: 256 threads, 6 cp16 each -------
    auto load_stage = [&](int s, int k0) {
        const uint32_t sA = sb + s * STG;
        const uint32_t sB = sA + A_BYTES;
        // A: 128 rows x 4 chunks
#pragma unroll
        for (int i = 0; i < 2; i++) {
            int t = tid + i * 256;
            int r = t >> 2, c = t & 3;
            cp16(sA + r * ROWB + c * 16, A + (size_t)r * LDA + k0 + c * 8);
        }
        // B: 256 rows x 4 chunks
#pragma unroll
        for (int i = 0; i < 4; i++) {
            int t = tid + i * 256;
            int r = t >> 2, c = t & 3;
            const __half* src;
            if (G1)
                src = (r < 128) ? B0 + (size_t)r * LDB + k0 + c * 8
                                : B1w + (size_t)(r - 128) * LDB + k0 + c * 8;
            else
                src = B0 + (size_t)r * LDB + k0 + c * 8;
            cp16(sB + r * ROWB + c * 16, src);
        }
    };

    load_stage(0, 0);  cp_commit();
    load_stage(1, 32); cp_commit();
    load_stage(2, 64); cp_commit();

    // warp layout: wm in {0,1} over M (64 rows each), wn in {0..3} over N
    const int wm = wid >> 2;
    const int wn = wid & 3;
    const int lr = lane & 15;          // ldmatrix row within 16
    const int lk = (lane >> 4) * 16;   // ldmatrix k-half byte offset

    // accumulators
    float acc0[4][4][4];               // G1: gate ; G2: n cols 0..31 of warp tile
    float acc1[4][4][4];               // G1: up   ; G2: n cols 32..63
#pragma unroll
    for (int i = 0; i < 4; i++)
#pragma unroll
        for (int j = 0; j < 4; j++)
#pragma unroll
            for (int q = 0; q < 4; q++) { acc0[i][j][q] = 0.f; acc1[i][j][q] = 0.f; }

    for (int kt = 0; kt < NK; kt++) {
        cp_wait2();
        __syncthreads();

        // issue next loads early (buffer (kt+3)&3 was consumed at iter kt-1)
        if (kt + 3 < NK) load_stage((kt + 3) & 3, (kt + 3) * 32);
        cp_commit();

        const uint32_t sA = sb + (kt & 3) * STG;
        const uint32_t sB = sA + A_BYTES;

        // A fragments: 64 rows x 32 k
        uint32_t af[4][2][4];
#pragma unroll
        for (int mt = 0; mt < 4; mt++)
#pragma unroll
            for (int kk = 0; kk < 2; kk++)
                ldsm4(af[mt][kk], sA + (wm * 64 + mt * 16 + lr) * ROWB + kk * 32 + lk);

        if (G1) {
            // B: w1 rows [wn*32, +32), w3 rows [128 + wn*32, +32)
            uint32_t b1[2][2][4], b3[2][2][4];
#pragma unroll
            for (int nt = 0; nt < 2; nt++)
#pragma unroll
                for (int kk = 0; kk < 2; kk++) {
                    ldsm4(b1[nt][kk], sB + (wn * 32 + nt * 16 + lr) * ROWB + kk * 32 + lk);
                    ldsm4(b3[nt][kk], sB + (128 + wn * 32 + nt * 16 + lr) * ROWB + kk * 32 + lk);
                }
#pragma unroll
            for (int mt = 0; mt < 4; mt++)
#pragma unroll
                for (int nt = 0; nt < 4; nt++) {
                    int n2 = nt >> 1, hi = nt & 1;
#pragma unroll
                    for (int kk = 0; kk < 2; kk++) {
                        mma16816(acc0[mt][nt], af[mt][kk], b1[n2][kk][hi], b1[n2][kk][hi + 2]);
                        mma16816(acc1[mt][nt], af[mt][kk], b3[n2][kk][hi], b3[n2][kk][hi + 2]);
                    }
                }
        } else {
            // B: 64 cols for this warp: rows [wn*64, +64)
            uint32_t bf[4][2][4];
#pragma unroll
            for (int nt = 0; nt < 4; nt++)
#pragma unroll
                for (int kk = 0; kk < 2; kk++)
                    ldsm4(bf[nt][kk], sB + (wn * 64 + nt * 16 + lr) * ROWB + kk * 32 + lk);
#pragma unroll
            for (int mt = 0; mt < 4; mt++)
#pragma unroll
                for (int nt = 0; nt < 4; nt++) {
                    int n2 = nt >> 1, hi = nt & 1;
#pragma unroll
                    for (int kk = 0; kk < 2; kk++) {
                        mma16816(acc0[mt][nt], af[mt][kk], bf[n2][kk][hi], bf[n2][kk][hi + 2]);
                        mma16816(acc1[mt][nt], af[mt][kk], bf[n2 + 2][kk][hi], bf[n2 + 2][kk][hi + 2]);
                    }
                }
        }
        __syncthreads();   // protect smem buffer reuse
    }

    // ---------------- epilogue ----------------
    const int r0 = m0 + wm * 64 + (lane >> 2);
    const int c0 = (lane & 3) * 2;

    if (G1) {
        // H fp16 tile [128 x 128] at (be, m0, n0); SwiGLU(acc0, acc1)
#pragma unroll
        for (int mt = 0; mt < 4; mt++) {
#pragma unroll
            for (int h = 0; h < 2; h++) {
                const size_t row = (size_t)be * C_ + r0 + mt * 16 + h * 8;
                __half* orow = g_hh + row * F_ + n0 + wn * 32 + c0;
#pragma unroll
                for (int nt = 0; nt < 4; nt++) {
                    float g0 = acc0[mt][nt][2 * h + 0], g1 = acc0[mt][nt][2 * h + 1];
                    float u0 = acc1[mt][nt][2 * h + 0], u1 = acc1[mt][nt][2 * h + 1];
                    float h0 = u0 * g0 / (1.0f + __expf(-g0));
                    float h1 = u1 * g1 / (1.0f + __expf(-g1));
                    *reinterpret_cast<__half2*>(orow + nt * 8) = __floats2half2_rn(h0, h1);
                }
            }
        }
    } else {
        // fp32 out tile [128 x 256]
#pragma unroll
        for (int mt = 0; mt < 4; mt++) {
#pragma unroll
            for (int h = 0; h < 2; h++) {
                const size_t row = (size_t)be * C_ + r0 + mt * 16 + h * 8;
                float* orow = out + row * D_ + n0 + wn * 64 + c0;
#pragma unroll
                for (int nt = 0; nt < 4; nt++) {
                    float2 v0 = make_float2(acc0[mt][nt][2 * h + 0], acc0[mt][nt][2 * h + 1]);
                    float2 v1 = make_float2(acc1[mt][nt][2 * h + 0], acc1[mt][nt][2 * h + 1]);
                    *reinterpret_cast<float2*>(orow + nt * 8)      = v0;
                    *reinterpret_cast<float2*>(orow + 32 + nt * 8) = v1;
                }
            }
        }
    }
}

// ---------------- launch ----------------
extern "C" void kernel_launch(void* const* d_in, const int* in_sizes, int n_in,
                              void* d_out, int out_size) {
    const float* x  = (const float*)d_in[0];
    const float* w1 = (const float*)d_in[1];
    const float* w3 = (const float*)d_in[2];
    const float* w2 = (const float*)d_in[3];
    float* out = (float*)d_out;

    void *pxh, *pw1t, *pw3t, *pw2t;
    cudaGetSymbolAddress(&pxh,  g_xh);
    cudaGetSymbolAddress(&pw1t, g_w1t);
    cudaGetSymbolAddress(&pw3t, g_w3t);
    cudaGetSymbolAddress(&pw2t, g_w2t);

    cudaFuncSetAttribute(gemm_mma<1>, cudaFuncAttributeMaxDynamicSharedMemorySize, DYNSM);
    cudaFuncSetAttribute(gemm_mma<0>, cudaFuncAttributeMaxDynamicSharedMemorySize, DYNSM);

    const int nx4 = (int)((size_t)B_ * E_ * C_ * D_ / 4);
    cvt_kernel<<<(nx4 + 255) / 256, 256>>>((const float4*)x, (__half2*)pxh, nx4);

    dim3 tb(32, 8);
    cvtT_kernel<<<dim3(F_ / 32, D_ / 32, E_), tb>>>(w1, (__half*)pw1t, D_, F_);
    cvtT_kernel<<<dim3(F_ / 32, D_ / 32, E_), tb>>>(w3, (__half*)pw3t, D_, F_);
    cvtT_kernel<<<dim3(D_ / 32, F_ / 32, E_), tb>>>(w2, (__half*)pw2t, F_, D_);

    gemm_mma<1><<<dim3(F_ / 128, C_ / 128, B_ * E_), 256, DYNSM>>>(nullptr);
    gemm_mma<0><<<dim3(D_ / 256, C_ / 128, B_ * E_), 256, DYNSM>>>(out);
}

// round 4
// speedup vs baseline: 1.1278x; 1.1278x over previous
#include <cuda_runtime.h>
#include <cuda_fp16.h>
#include <cstdint>

// ---------------- problem dims ----------------
constexpr int B_ = 4, E_ = 8, C_ = 2048, D_ = 1024, F_ = 2816;

// ---------------- device scratch (allocation-free) ----------------
__device__ __half g_xh [(size_t)B_ * E_ * C_ * D_];   // X fp16 [be][C][D]
__device__ __half g_w1t[(size_t)E_ * F_ * D_];        // w1^T fp16 [e][F][D]
__device__ __half g_w3t[(size_t)E_ * F_ * D_];        // w3^T fp16 [e][F][D]
__device__ __half g_w2t[(size_t)E_ * D_ * F_];        // w2^T fp16 [e][D][F]
__device__ __half g_hh [(size_t)B_ * E_ * C_ * F_];   // H fp16 [be][C][F]

// ---------------- PTX helpers ----------------
__device__ __forceinline__ uint32_t smem_u32(const void* p) {
    return (uint32_t)__cvta_generic_to_shared(p);
}
__device__ __forceinline__ void cp16(uint32_t saddr, const void* g) {
    asm volatile("cp.async.cg.shared.global [%0], [%1], 16;\n" ::"r"(saddr), "l"(g));
}
__device__ __forceinline__ void cp_commit() {
    asm volatile("cp.async.commit_group;\n");
}
__device__ __forceinline__ void cp_wait2() {
    asm volatile("cp.async.wait_group 2;\n");
}
__device__ __forceinline__ void ldsm4(uint32_t* r, uint32_t addr) {
    asm volatile("ldmatrix.sync.aligned.m8n8.x4.shared.b16 {%0,%1,%2,%3}, [%4];"
                 : "=r"(r[0]), "=r"(r[1]), "=r"(r[2]), "=r"(r[3])
                 : "r"(addr));
}
__device__ __forceinline__ void mma16816(float* d, const uint32_t* a, uint32_t b0, uint32_t b1) {
    asm volatile(
        "mma.sync.aligned.m16n8k16.row.col.f32.f16.f16.f32 "
        "{%0,%1,%2,%3}, {%4,%5,%6,%7}, {%8,%9}, {%0,%1,%2,%3};"
        : "+f"(d[0]), "+f"(d[1]), "+f"(d[2]), "+f"(d[3])
        : "r"(a[0]), "r"(a[1]), "r"(a[2]), "r"(a[3]), "r"(b0), "r"(b1));
}

// ---------------- convert kernels ----------------
__global__ void cvt_kernel(const float4* __restrict__ in, __half2* __restrict__ out, int n4) {
    int i = blockIdx.x * 256 + threadIdx.x;
    if (i >= n4) return;
    float4 v = in[i];
    out[2 * i + 0] = __floats2half2_rn(v.x, v.y);
    out[2 * i + 1] = __floats2half2_rn(v.z, v.w);
}

// in: [R, Ccols] fp32 per expert  ->  out: [Ccols, R] fp16 per expert
__global__ void cvtT_kernel(const float* __restrict__ in, __half* __restrict__ out,
                            int R, int Ccols) {
    __shared__ float t[32][33];
    const float* ine  = in  + (size_t)blockIdx.z * R * Ccols;
    __half*      oute = out + (size_t)blockIdx.z * R * Ccols;
    int c0 = blockIdx.x * 32, r0 = blockIdx.y * 32;
    int tx = threadIdx.x, ty = threadIdx.y;   // 32 x 8
#pragma unroll
    for (int i = 0; i < 4; i++)
        t[ty + 8 * i][tx] = ine[(size_t)(r0 + ty + 8 * i) * Ccols + c0 + tx];
    __syncthreads();
#pragma unroll
    for (int i = 0; i < 4; i++)
        oute[(size_t)(c0 + ty + 8 * i) * R + r0 + tx] = __float2half_rn(t[tx][ty + 8 * i]);
}

// ============================================================
// mma.sync GEMM, 256 threads, CTA: 128 x 128, BK=32, 4 stages, 2 CTAs/SM.
// SMEM rows: 32 halfs (64B) at 80B stride (ldmatrix conflict-free).
// Warp layout: 2 (M) x 4 (N); warp tile 64 x 32.
// GEMM1 (G1=1): A=X, B=[w1t 64 rows ; w3t 64 rows]; warp: 64x16 gate + 64x16 up,
//               SwiGLU epilogue -> H fp16 [128 x 64] tile.
// GEMM2 (G1=0): A=H, B=w2t 128 rows; warp 64x32 -> out fp32 [128 x 128] tile.
// ============================================================
constexpr int ROWB  = 80;
constexpr int STG   = 256 * ROWB;    // 128 A rows + 128 B rows = 20480 B
constexpr int DYNSM = 4 * STG;       // 81920

template <int G1>
__global__ __launch_bounds__(256, 2) void gemm_mma(float* __restrict__ out) {
    extern __shared__ __align__(128) char smem[];

    const int tid  = threadIdx.x;
    const int wid  = tid >> 5;
    const int lane = tid & 31;
    const int be   = blockIdx.z, e = be & 7;
    const int m0   = blockIdx.y * 128;
    const int n0   = blockIdx.x * (G1 ? 64 : 128);

    constexpr int LD  = G1 ? D_ : F_;               // k extent of A and B rows
    constexpr int NK  = G1 ? (D_ / 32) : (F_ / 32); // 32 : 88

    const __half* A = (G1 ? g_xh : g_hh) + ((size_t)be * C_ + m0) * LD;
    const __half* B0;
    const __half* B1w = nullptr;
    if (G1) {
        B0  = g_w1t + (size_t)e * F_ * D_ + (size_t)n0 * D_;
        B1w = g_w3t + (size_t)e * F_ * D_ + (size_t)n0 * D_;
    } else {
        B0 = g_w2t + (size_t)e * D_ * F_ + (size_t)n0 * F_;
    }

    const uint32_t sb = smem_u32(smem);

    // ------- stage loader: 256 threads x 4 cp16 -------
    auto load_stage = [&](int s, int k0) {
        const uint32_t base = sb + s * STG;
#pragma unroll
        for (int i = 0; i < 4; i++) {
            int t = tid + i * 256;          // 0..1023
            int r = t >> 2, c = t & 3;      // r 0..255
            const __half* src;
            if (r < 128) {
                src = A + (size_t)r * LD + k0 + c * 8;
            } else {
                int n = r - 128;            // 0..127
                if (G1)
                    src = (n < 64) ? B0 + (size_t)n * D_ + k0 + c * 8
                                   : B1w + (size_t)(n - 64) * D_ + k0 + c * 8;
                else
                    src = B0 + (size_t)n * LD + k0 + c * 8;
            }
            cp16(base + r * ROWB + c * 16, src);
        }
    };

    load_stage(0, 0);  cp_commit();
    load_stage(1, 32); cp_commit();
    load_stage(2, 64); cp_commit();

    const int wm = wid >> 2;           // 0..1 (M)
    const int wn = wid & 3;            // 0..3 (N)
    const int lr = lane & 15;
    const int lk = (lane >> 4) * 16;

    // acc0: G1 gate / G2 n-cols [wn*32, +16); acc1: G1 up / G2 n-cols [wn*32+16, +16)
    float acc0[4][2][4], acc1[4][2][4];
#pragma unroll
    for (int i = 0; i < 4; i++)
#pragma unroll
        for (int j = 0; j < 2; j++)
#pragma unroll
            for (int q = 0; q < 4; q++) { acc0[i][j][q] = 0.f; acc1[i][j][q] = 0.f; }

    for (int kt = 0; kt < NK; kt++) {
        cp_wait2();
        __syncthreads();

        if (kt + 3 < NK) load_stage((kt + 3) & 3, (kt + 3) * 32);
        cp_commit();

        const uint32_t sA = sb + (kt & 3) * STG;
        const uint32_t sB = sA + 128 * ROWB;

#pragma unroll
        for (int kk = 0; kk < 2; kk++) {
            uint32_t af[4][4];
#pragma unroll
            for (int mt = 0; mt < 4; mt++)
                ldsm4(af[mt], sA + (wm * 64 + mt * 16 + lr) * ROWB + kk * 32 + lk);

            uint32_t b0r[4], b1r[4];
            if (G1) {
                ldsm4(b0r, sB + (wn * 16 + lr) * ROWB + kk * 32 + lk);         // gate
                ldsm4(b1r, sB + (64 + wn * 16 + lr) * ROWB + kk * 32 + lk);    // up
            } else {
                ldsm4(b0r, sB + (wn * 32 + lr) * ROWB + kk * 32 + lk);
                ldsm4(b1r, sB + (wn * 32 + 16 + lr) * ROWB + kk * 32 + lk);
            }
#pragma unroll
            for (int mt = 0; mt < 4; mt++)
#pragma unroll
                for (int hi = 0; hi < 2; hi++) {
                    mma16816(acc0[mt][hi], af[mt], b0r[hi], b0r[hi + 2]);
                    mma16816(acc1[mt][hi], af[mt], b1r[hi], b1r[hi + 2]);
                }
        }
        __syncthreads();
    }

    // ---------------- epilogue ----------------
    const int rbase = m0 + wm * 64 + (lane >> 2);
    const int c0    = (lane & 3) * 2;

    if (G1) {
        // SwiGLU -> H fp16, warp tile 64 rows x 16 cols at n0 + wn*16
#pragma unroll
        for (int mt = 0; mt < 4; mt++) {
#pragma unroll
            for (int h = 0; h < 2; h++) {
                const size_t row = (size_t)be * C_ + rbase + mt * 16 + h * 8;
                __half* orow = g_hh + row * F_ + n0 + wn * 16 + c0;
#pragma unroll
                for (int hi = 0; hi < 2; hi++) {
                    float g0 = acc0[mt][hi][2 * h + 0], g1 = acc0[mt][hi][2 * h + 1];
                    float u0 = acc1[mt][hi][2 * h + 0], u1 = acc1[mt][hi][2 * h + 1];
                    float h0 = u0 * g0 / (1.0f + __expf(-g0));
                    float h1 = u1 * g1 / (1.0f + __expf(-g1));
                    *reinterpret_cast<__half2*>(orow + hi * 8) = __floats2half2_rn(h0, h1);
                }
            }
        }
    } else {
        // fp32 out, warp tile 64 rows x 32 cols at n0 + wn*32
#pragma unroll
        for (int mt = 0; mt < 4; mt++) {
#pragma unroll
            for (int h = 0; h < 2; h++) {
                const size_t row = (size_t)be * C_ + rbase + mt * 16 + h * 8;
                float* orow = out + row * D_ + n0 + wn * 32 + c0;
#pragma unroll
                for (int hi = 0; hi < 2; hi++) {
                    *reinterpret_cast<float2*>(orow + hi * 8) =
                        make_float2(acc0[mt][hi][2 * h + 0], acc0[mt][hi][2 * h + 1]);
                    *reinterpret_cast<float2*>(orow + 16 + hi * 8) =
                        make_float2(acc1[mt][hi][2 * h + 0], acc1[mt][hi][2 * h + 1]);
                }
            }
        }
    }
}

// ---------------- launch ----------------
extern "C" void kernel_launch(void* const* d_in, const int* in_sizes, int n_in,
                              void* d_out, int out_size) {
    const float* x  = (const float*)d_in[0];
    const float* w1 = (const float*)d_in[1];
    const float* w3 = (const float*)d_in[2];
    const float* w2 = (const float*)d_in[3];
    float* out = (float*)d_out;

    void *pxh, *pw1t, *pw3t, *pw2t;
    cudaGetSymbolAddress(&pxh,  g_xh);
    cudaGetSymbolAddress(&pw1t, g_w1t);
    cudaGetSymbolAddress(&pw3t, g_w3t);
    cudaGetSymbolAddress(&pw2t, g_w2t);

    cudaFuncSetAttribute(gemm_mma<1>, cudaFuncAttributeMaxDynamicSharedMemorySize, DYNSM);
    cudaFuncSetAttribute(gemm_mma<0>, cudaFuncAttributeMaxDynamicSharedMemorySize, DYNSM);

    const int nx4 = (int)((size_t)B_ * E_ * C_ * D_ / 4);
    cvt_kernel<<<(nx4 + 255) / 256, 256>>>((const float4*)x, (__half2*)pxh, nx4);

    dim3 tb(32, 8);
    cvtT_kernel<<<dim3(F_ / 32, D_ / 32, E_), tb>>>(w1, (__half*)pw1t, D_, F_);
    cvtT_kernel<<<dim3(F_ / 32, D_ / 32, E_), tb>>>(w3, (__half*)pw3t, D_, F_);
    cvtT_kernel<<<dim3(D_ / 32, F_ / 32, E_), tb>>>(w2, (__half*)pw2t, F_, D_);

    gemm_mma<1><<<dim3(F_ / 64, C_ / 128, B_ * E_), 256, DYNSM>>>(nullptr);
    gemm_mma<0><<<dim3(D_ / 128, C_ / 128, B_ * E_), 256, DYNSM>>>(out);
}

// round 5
// speedup vs baseline: 1.2507x; 1.1089x over previous
#include <cuda_runtime.h>
#include <cuda_fp16.h>
#include <cstdint>

// ---------------- problem dims ----------------
constexpr int B_ = 4, E_ = 8, C_ = 2048, D_ = 1024, F_ = 2816;

// ---------------- device scratch (allocation-free) ----------------
__device__ __half g_xh [(size_t)B_ * E_ * C_ * D_];   // X fp16 [be][C][D]
__device__ __half g_w1t[(size_t)E_ * F_ * D_];        // w1^T fp16 [e][F][D]
__device__ __half g_w3t[(size_t)E_ * F_ * D_];        // w3^T fp16 [e][F][D]
__device__ __half g_w2t[(size_t)E_ * D_ * F_];        // w2^T fp16 [e][D][F]
__device__ __half g_hh [(size_t)B_ * E_ * C_ * F_];   // H fp16 [be][C][F]

// ---------------- PTX helpers ----------------
__device__ __forceinline__ uint32_t smem_u32(const void* p) {
    return (uint32_t)__cvta_generic_to_shared(p);
}
__device__ __forceinline__ void cp16(uint32_t saddr, const void* g) {
    asm volatile("cp.async.cg.shared.global [%0], [%1], 16;\n" ::"r"(saddr), "l"(g));
}
__device__ __forceinline__ void cp_commit() {
    asm volatile("cp.async.commit_group;\n");
}
__device__ __forceinline__ void cp_wait1() {
    asm volatile("cp.async.wait_group 1;\n");
}
__device__ __forceinline__ void ldsm4(uint32_t* r, uint32_t addr) {
    asm volatile("ldmatrix.sync.aligned.m8n8.x4.shared.b16 {%0,%1,%2,%3}, [%4];"
                 : "=r"(r[0]), "=r"(r[1]), "=r"(r[2]), "=r"(r[3])
                 : "r"(addr));
}
__device__ __forceinline__ void mma16816(float* d, const uint32_t* a, uint32_t b0, uint32_t b1) {
    asm volatile(
        "mma.sync.aligned.m16n8k16.row.col.f32.f16.f16.f32 "
        "{%0,%1,%2,%3}, {%4,%5,%6,%7}, {%8,%9}, {%0,%1,%2,%3};"
        : "+f"(d[0]), "+f"(d[1]), "+f"(d[2]), "+f"(d[3])
        : "r"(a[0]), "r"(a[1]), "r"(a[2]), "r"(a[3]), "r"(b0), "r"(b1));
}

// ---------------- convert kernels ----------------
__global__ void cvt_kernel(const float4* __restrict__ in, __half2* __restrict__ out, int n4) {
    int i = blockIdx.x * 256 + threadIdx.x;
    if (i >= n4) return;
    float4 v = in[i];
    out[2 * i + 0] = __floats2half2_rn(v.x, v.y);
    out[2 * i + 1] = __floats2half2_rn(v.z, v.w);
}

// in: [R, Ccols] fp32 per expert  ->  out: [Ccols, R] fp16 per expert
__global__ void cvtT_kernel(const float* __restrict__ in, __half* __restrict__ out,
                            int R, int Ccols) {
    __shared__ float t[32][33];
    const float* ine  = in  + (size_t)blockIdx.z * R * Ccols;
    __half*      oute = out + (size_t)blockIdx.z * R * Ccols;
    int c0 = blockIdx.x * 32, r0 = blockIdx.y * 32;
    int tx = threadIdx.x, ty = threadIdx.y;   // 32 x 8
#pragma unroll
    for (int i = 0; i < 4; i++)
        t[ty + 8 * i][tx] = ine[(size_t)(r0 + ty + 8 * i) * Ccols + c0 + tx];
    __syncthreads();
#pragma unroll
    for (int i = 0; i < 4; i++)
        oute[(size_t)(c0 + ty + 8 * i) * R + r0 + tx] = __float2half_rn(t[tx][ty + 8 * i]);
}

// ============================================================
// mma.sync GEMM, 512 threads, CTA tile 128(M) x 256(B-rows), BK=64, 3 stages.
// SMEM rows: 64 halfs (128B) at 144B stride -> ldmatrix conflict-free.
// Warp grid 4(M) x 4(N): warp owns 32 M-rows and 64 B-rows.
// GEMM1 (G1=1): B = [128 w1t rows ; 128 w3t rows] for F-cols [nf0, nf0+128).
//               Warp wn owns gate rows [wn*32,+32) AND up rows [128+wn*32,+32)
//               -> SwiGLU in registers -> H fp16 tile 128 x 128.
// GEMM2 (G1=0): B = 256 w2t rows -> out fp32 tile 128 x 256.
// ============================================================
constexpr int ROWB  = 144;
constexpr int STG   = 384 * ROWB;    // 55296 B
constexpr int DYNSM = 3 * STG;       // 165888 B

template <int G1>
__global__ __launch_bounds__(512, 1) void gemm_mma(float* __restrict__ out) {
    extern __shared__ __align__(128) char smem[];

    const int tid  = threadIdx.x;
    const int wid  = tid >> 5;
    const int lane = tid & 31;
    const int be   = blockIdx.z, e = be & 7;
    const int m0   = blockIdx.y * 128;
    const int n0   = blockIdx.x * (G1 ? 128 : 256);   // G1: F-col block of 128

    constexpr int LD = G1 ? D_ : F_;
    constexpr int NK = G1 ? (D_ / 64) : (F_ / 64);    // 16 : 44

    const __half* A = (G1 ? g_xh : g_hh) + ((size_t)be * C_ + m0) * LD;
    const __half* B0;
    const __half* B1w = nullptr;
    if (G1) {
        B0  = g_w1t + (size_t)e * F_ * D_ + (size_t)n0 * D_;
        B1w = g_w3t + (size_t)e * F_ * D_ + (size_t)n0 * D_;
    } else {
        B0 = g_w2t + (size_t)e * D_ * F_ + (size_t)n0 * F_;
    }

    const uint32_t sb = smem_u32(smem);

    // ------- stage loader: 512 threads x 6 cp16 (384 rows x 8 chunks) -------
    auto load_stage = [&](int s, int k0) {
        const uint32_t base = sb + s * STG;
#pragma unroll
        for (int i = 0; i < 6; i++) {
            int t = tid + i * 512;
            int r = t >> 3, c = t & 7;      // r 0..383, c 0..7
            const __half* src;
            if (r < 128) {
                src = A + (size_t)r * LD + k0 + c * 8;
            } else {
                int n = r - 128;            // 0..255
                if (G1)
                    src = (n < 128) ? B0 + (size_t)n * D_ + k0 + c * 8
                                    : B1w + (size_t)(n - 128) * D_ + k0 + c * 8;
                else
                    src = B0 + (size_t)n * F_ + k0 + c * 8;
            }
            cp16(base + r * ROWB + c * 16, src);
        }
    };

    load_stage(0, 0);  cp_commit();
    load_stage(1, 64); cp_commit();

    const int wm = wid >> 2;           // 0..3 : M rows [wm*32, +32)
    const int wn = wid & 3;            // 0..3
    const int lr = lane & 15;
    const int lk = (lane >> 4) * 16;

    // acc0: G1 gate / G2 cols [wn*64, +32) ; acc1: G1 up / G2 cols [wn*64+32, +32)
    float acc0[2][2][2][4], acc1[2][2][2][4];
#pragma unroll
    for (int a = 0; a < 2; a++)
#pragma unroll
        for (int b = 0; b < 2; b++)
#pragma unroll
            for (int c = 0; c < 2; c++)
#pragma unroll
                for (int q = 0; q < 4; q++) { acc0[a][b][c][q] = 0.f; acc1[a][b][c][q] = 0.f; }

    for (int kt = 0; kt < NK; kt++) {
        const int s = kt % 3;
        cp_wait1();
        __syncthreads();

        if (kt + 2 < NK) load_stage((kt + 2) % 3, (kt + 2) * 64);
        cp_commit();

        const uint32_t sA = sb + s * STG;
        const uint32_t sB = sA + 128 * ROWB;

#pragma unroll
        for (int kk = 0; kk < 4; kk++) {
            uint32_t af[2][4];
#pragma unroll
            for (int mt = 0; mt < 2; mt++)
                ldsm4(af[mt], sA + (wm * 32 + mt * 16 + lr) * ROWB + kk * 32 + lk);

            uint32_t b0r[2][4], b1r[2][4];
#pragma unroll
            for (int nt = 0; nt < 2; nt++) {
                if (G1) {
                    ldsm4(b0r[nt], sB + (wn * 32 + nt * 16 + lr) * ROWB + kk * 32 + lk);
                    ldsm4(b1r[nt], sB + (128 + wn * 32 + nt * 16 + lr) * ROWB + kk * 32 + lk);
                } else {
                    ldsm4(b0r[nt], sB + (wn * 64 + nt * 16 + lr) * ROWB + kk * 32 + lk);
                    ldsm4(b1r[nt], sB + (wn * 64 + 32 + nt * 16 + lr) * ROWB + kk * 32 + lk);
                }
            }
#pragma unroll
            for (int mt = 0; mt < 2; mt++)
#pragma unroll
                for (int nt = 0; nt < 2; nt++)
#pragma unroll
                    for (int hi = 0; hi < 2; hi++) {
                        mma16816(acc0[mt][nt][hi], af[mt], b0r[nt][hi], b0r[nt][hi + 2]);
                        mma16816(acc1[mt][nt][hi], af[mt], b1r[nt][hi], b1r[nt][hi + 2]);
                    }
        }
        __syncthreads();
    }

    // ---------------- epilogue ----------------
    const int rbase = m0 + wm * 32 + (lane >> 2);
    const int c0    = (lane & 3) * 2;

    if (G1) {
        // SwiGLU -> H fp16, warp tile 32 rows x 32 F-cols at n0 + wn*32
#pragma unroll
        for (int mt = 0; mt < 2; mt++) {
#pragma unroll
            for (int h = 0; h < 2; h++) {
                const size_t row = (size_t)be * C_ + rbase + mt * 16 + h * 8;
                __half* orow = g_hh + row * F_ + n0 + wn * 32 + c0;
#pragma unroll
                for (int nt = 0; nt < 2; nt++)
#pragma unroll
                    for (int hi = 0; hi < 2; hi++) {
                        float g0 = acc0[mt][nt][hi][2 * h + 0], g1 = acc0[mt][nt][hi][2 * h + 1];
                        float u0 = acc1[mt][nt][hi][2 * h + 0], u1 = acc1[mt][nt][hi][2 * h + 1];
                        float h0 = u0 * g0 / (1.0f + __expf(-g0));
                        float h1 = u1 * g1 / (1.0f + __expf(-g1));
                        *reinterpret_cast<__half2*>(orow + nt * 16 + hi * 8) =
                            __floats2half2_rn(h0, h1);
                    }
            }
        }
    } else {
        // fp32 out, warp tile 32 rows x 64 cols at n0 + wn*64
#pragma unroll
        for (int mt = 0; mt < 2; mt++) {
#pragma unroll
            for (int h = 0; h < 2; h++) {
                const size_t row = (size_t)be * C_ + rbase + mt * 16 + h * 8;
                float* orow = out + row * D_ + n0 + wn * 64 + c0;
#pragma unroll
                for (int nt = 0; nt < 2; nt++)
#pragma unroll
                    for (int hi = 0; hi < 2; hi++) {
                        *reinterpret_cast<float2*>(orow + nt * 16 + hi * 8) =
                            make_float2(acc0[mt][nt][hi][2 * h + 0], acc0[mt][nt][hi][2 * h + 1]);
                        *reinterpret_cast<float2*>(orow + 32 + nt * 16 + hi * 8) =
                            make_float2(acc1[mt][nt][hi][2 * h + 0], acc1[mt][nt][hi][2 * h + 1]);
                    }
            }
        }
    }
}

// ---------------- launch ----------------
extern "C" void kernel_launch(void* const* d_in, const int* in_sizes, int n_in,
                              void* d_out, int out_size) {
    const float* x  = (const float*)d_in[0];
    const float* w1 = (const float*)d_in[1];
    const float* w3 = (const float*)d_in[2];
    const float* w2 = (const float*)d_in[3];
    float* out = (float*)d_out;

    void *pxh, *pw1t, *pw3t, *pw2t;
    cudaGetSymbolAddress(&pxh,  g_xh);
    cudaGetSymbolAddress(&pw1t, g_w1t);
    cudaGetSymbolAddress(&pw3t, g_w3t);
    cudaGetSymbolAddress(&pw2t, g_w2t);

    cudaFuncSetAttribute(gemm_mma<1>, cudaFuncAttributeMaxDynamicSharedMemorySize, DYNSM);
    cudaFuncSetAttribute(gemm_mma<0>, cudaFuncAttributeMaxDynamicSharedMemorySize, DYNSM);

    const int nx4 = (int)((size_t)B_ * E_ * C_ * D_ / 4);
    cvt_kernel<<<(nx4 + 255) / 256, 256>>>((const float4*)x, (__half2*)pxh, nx4);

    dim3 tb(32, 8);
    cvtT_kernel<<<dim3(F_ / 32, D_ / 32, E_), tb>>>(w1, (__half*)pw1t, D_, F_);
    cvtT_kernel<<<dim3(F_ / 32, D_ / 32, E_), tb>>>(w3, (__half*)pw3t, D_, F_);
    cvtT_kernel<<<dim3(D_ / 32, F_ / 32, E_), tb>>>(w2, (__half*)pw2t, F_, D_);

    gemm_mma<1><<<dim3(F_ / 128, C_ / 128, B_ * E_), 512, DYNSM>>>(nullptr);
    gemm_mma<0><<<dim3(D_ / 256, C_ / 128, B_ * E_), 512, DYNSM>>>(out);
}